// round 3
// baseline (speedup 1.0000x reference)
#include <cuda_runtime.h>

#define BATCH 16
#define SEQ   512
#define HID   768
#define NHEAD 12
#define HD    64
#define MROWS (BATCH*SEQ)   /* 8192 */
#define ATT_SCALE 0.03608439182435161f  /* 768^-0.5 */

// Scratch (module-load allocated, allowed)
__device__ float g_Q[MROWS*HID];
__device__ float g_K[MROWS*HID];
__device__ float g_V[MROWS*HID];
__device__ float g_O[MROWS*HID];

// ---------------------------------------------------------------------------
// C[M x Nout] = A[M x K] @ W[Nout x K]^T (+ bias)   — "NT" layout, fp32
// 128x128 block tile, BK=16, 8x8 per thread, 256 threads
// ---------------------------------------------------------------------------
__global__ __launch_bounds__(256) void sgemm_nt(
    const float* __restrict__ A, const float* __restrict__ W,
    const float* __restrict__ bias, float* __restrict__ C,
    int M, int Nout, int K)
{
    __shared__ float As[16][132];
    __shared__ float Ws[16][132];
    const int tx = threadIdx.x, ty = threadIdx.y;
    const int tid = ty * 16 + tx;
    const int lrow = tid >> 2;            // 0..63
    const int lcol = (tid & 3) << 2;      // 0,4,8,12

    const float* Ab = A + (size_t)blockIdx.y * 128 * K;
    const float* Wb = W + (size_t)blockIdx.x * 128 * K;

    float acc[8][8];
#pragma unroll
    for (int i = 0; i < 8; i++)
#pragma unroll
        for (int j = 0; j < 8; j++) acc[i][j] = 0.f;

    for (int kt = 0; kt < K; kt += 16) {
        float4 a0 = *(const float4*)(Ab + (size_t)lrow * K + kt + lcol);
        float4 a1 = *(const float4*)(Ab + (size_t)(lrow + 64) * K + kt + lcol);
        float4 w0 = *(const float4*)(Wb + (size_t)lrow * K + kt + lcol);
        float4 w1 = *(const float4*)(Wb + (size_t)(lrow + 64) * K + kt + lcol);
        __syncthreads();
        As[lcol + 0][lrow] = a0.x; As[lcol + 1][lrow] = a0.y;
        As[lcol + 2][lrow] = a0.z; As[lcol + 3][lrow] = a0.w;
        As[lcol + 0][lrow + 64] = a1.x; As[lcol + 1][lrow + 64] = a1.y;
        As[lcol + 2][lrow + 64] = a1.z; As[lcol + 3][lrow + 64] = a1.w;
        Ws[lcol + 0][lrow] = w0.x; Ws[lcol + 1][lrow] = w0.y;
        Ws[lcol + 2][lrow] = w0.z; Ws[lcol + 3][lrow] = w0.w;
        Ws[lcol + 0][lrow + 64] = w1.x; Ws[lcol + 1][lrow + 64] = w1.y;
        Ws[lcol + 2][lrow + 64] = w1.z; Ws[lcol + 3][lrow + 64] = w1.w;
        __syncthreads();
#pragma unroll
        for (int kk = 0; kk < 16; kk++) {
            float af[8], bf[8];
            *(float4*)&af[0] = *(const float4*)&As[kk][ty * 8];
            *(float4*)&af[4] = *(const float4*)&As[kk][ty * 8 + 4];
            *(float4*)&bf[0] = *(const float4*)&Ws[kk][tx * 8];
            *(float4*)&bf[4] = *(const float4*)&Ws[kk][tx * 8 + 4];
#pragma unroll
            for (int i = 0; i < 8; i++)
#pragma unroll
                for (int j = 0; j < 8; j++)
                    acc[i][j] += af[i] * bf[j];
        }
    }

    const int row0 = blockIdx.y * 128 + ty * 8;
    const int col0 = blockIdx.x * 128 + tx * 8;
    float bb[8] = {0, 0, 0, 0, 0, 0, 0, 0};
    if (bias) {
        *(float4*)&bb[0] = *(const float4*)(bias + col0);
        *(float4*)&bb[4] = *(const float4*)(bias + col0 + 4);
    }
#pragma unroll
    for (int i = 0; i < 8; i++) {
        float4 r0 = make_float4(acc[i][0] + bb[0], acc[i][1] + bb[1],
                                acc[i][2] + bb[2], acc[i][3] + bb[3]);
        float4 r1 = make_float4(acc[i][4] + bb[4], acc[i][5] + bb[5],
                                acc[i][6] + bb[6], acc[i][7] + bb[7]);
        *(float4*)(C + (size_t)(row0 + i) * Nout + col0) = r0;
        *(float4*)(C + (size_t)(row0 + i) * Nout + col0 + 4) = r1;
    }
}

// ---------------------------------------------------------------------------
// Flash attention with additive bias.
// Block: 64 query rows of one (b,h). 16x16 threads, 4x4 per-thread tiles.
// smem: q^T[64d][68], k^T[64d][68], v[64m][68], p^T[64m][68]  (69632 B dyn)
// ---------------------------------------------------------------------------
__global__ __launch_bounds__(256) void attn_kernel(
    const float* __restrict__ Q, const float* __restrict__ K,
    const float* __restrict__ V, const float* __restrict__ bias,
    float* __restrict__ O)
{
    extern __shared__ float sm[];
    float* q_sT = sm;                 // [d][row]
    float* k_sT = sm + 64 * 68;       // [d][col]
    float* v_s  = sm + 2 * 64 * 68;   // [col][d]
    float* p_sT = sm + 3 * 64 * 68;   // [col][row]

    const int b = blockIdx.z, h = blockIdx.y;
    const int n0 = blockIdx.x * 64;
    const int tx = threadIdx.x, ty = threadIdx.y;
    const int tid = ty * 16 + tx;
    const int dl = tid & 63;          // 0..63
    const int rl = tid >> 6;          // 0..3

    // load Q tile transposed
    {
        const float* qb = Q + ((size_t)(b * SEQ + n0)) * HID + h * HD;
#pragma unroll
        for (int rr = rl; rr < 64; rr += 4)
            q_sT[dl * 68 + rr] = qb[rr * HID + dl];
    }

    float m_i[4], l_i[4], acc[4][4];
#pragma unroll
    for (int i = 0; i < 4; i++) {
        m_i[i] = -1e30f; l_i[i] = 0.f;
#pragma unroll
        for (int j = 0; j < 4; j++) acc[i][j] = 0.f;
    }

    for (int mt = 0; mt < 8; mt++) {
        const int m0 = mt * 64;
        __syncthreads();   // prev-iter smem reads done
        {
            const float* kb = K + ((size_t)(b * SEQ + m0)) * HID + h * HD;
            const float* vb = V + ((size_t)(b * SEQ + m0)) * HID + h * HD;
#pragma unroll
            for (int cc = rl; cc < 64; cc += 4) {
                k_sT[dl * 68 + cc] = kb[cc * HID + dl];
                v_s[cc * 68 + dl]  = vb[cc * HID + dl];
            }
        }
        __syncthreads();

        // S = Q K^T
        float s[4][4];
#pragma unroll
        for (int i = 0; i < 4; i++)
#pragma unroll
            for (int j = 0; j < 4; j++) s[i][j] = 0.f;
#pragma unroll 16
        for (int kk = 0; kk < 64; kk++) {
            float4 a = *(const float4*)&q_sT[kk * 68 + ty * 4];
            float4 kf = *(const float4*)&k_sT[kk * 68 + tx * 4];
            float af[4] = {a.x, a.y, a.z, a.w};
            float bf[4] = {kf.x, kf.y, kf.z, kf.w};
#pragma unroll
            for (int i = 0; i < 4; i++)
#pragma unroll
                for (int j = 0; j < 4; j++) s[i][j] += af[i] * bf[j];
        }
        // scale + bias
#pragma unroll
        for (int i = 0; i < 4; i++) {
            float4 bb = *(const float4*)(bias +
                ((size_t)(b * SEQ + n0 + ty * 4 + i)) * SEQ + m0 + tx * 4);
            s[i][0] = s[i][0] * ATT_SCALE + bb.x;
            s[i][1] = s[i][1] * ATT_SCALE + bb.y;
            s[i][2] = s[i][2] * ATT_SCALE + bb.z;
            s[i][3] = s[i][3] * ATT_SCALE + bb.w;
        }
        // online softmax update (row stats shared across the 16-lane tx group)
#pragma unroll
        for (int i = 0; i < 4; i++) {
            float tm = fmaxf(fmaxf(s[i][0], s[i][1]), fmaxf(s[i][2], s[i][3]));
#pragma unroll
            for (int off = 8; off > 0; off >>= 1)
                tm = fmaxf(tm, __shfl_xor_sync(0xffffffffu, tm, off));
            float mn = fmaxf(m_i[i], tm);
            float p0 = __expf(s[i][0] - mn);
            float p1 = __expf(s[i][1] - mn);
            float p2 = __expf(s[i][2] - mn);
            float p3 = __expf(s[i][3] - mn);
            float rs = (p0 + p1) + (p2 + p3);
#pragma unroll
            for (int off = 8; off > 0; off >>= 1)
                rs += __shfl_xor_sync(0xffffffffu, rs, off);
            float al = __expf(m_i[i] - mn);
            l_i[i] = l_i[i] * al + rs;
            m_i[i] = mn;
            acc[i][0] *= al; acc[i][1] *= al; acc[i][2] *= al; acc[i][3] *= al;
            p_sT[(tx * 4 + 0) * 68 + ty * 4 + i] = p0;
            p_sT[(tx * 4 + 1) * 68 + ty * 4 + i] = p1;
            p_sT[(tx * 4 + 2) * 68 + ty * 4 + i] = p2;
            p_sT[(tx * 4 + 3) * 68 + ty * 4 + i] = p3;
        }
        __syncthreads();
        // O += P V
#pragma unroll 8
        for (int c = 0; c < 64; c++) {
            float4 pa = *(const float4*)&p_sT[c * 68 + ty * 4];
            float4 vv = *(const float4*)&v_s[c * 68 + tx * 4];
            float pf[4] = {pa.x, pa.y, pa.z, pa.w};
            float vf[4] = {vv.x, vv.y, vv.z, vv.w};
#pragma unroll
            for (int i = 0; i < 4; i++)
#pragma unroll
                for (int j = 0; j < 4; j++) acc[i][j] += pf[i] * vf[j];
        }
    }

    float* ob = O + ((size_t)(b * SEQ + n0 + ty * 4)) * HID + h * HD + tx * 4;
#pragma unroll
    for (int i = 0; i < 4; i++) {
        float inv = 1.0f / l_i[i];
        float4 r = make_float4(acc[i][0] * inv, acc[i][1] * inv,
                               acc[i][2] * inv, acc[i][3] * inv);
        *(float4*)(ob + (size_t)i * HID) = r;
    }
}

// ---------------------------------------------------------------------------
extern "C" void kernel_launch(void* const* d_in, const int* in_sizes, int n_in,
                              void* d_out, int out_size)
{
    const float* x  = (const float*)d_in[0];
    const float* eb = (const float*)d_in[1];
    const float* Wq = (const float*)d_in[2];
    const float* Wk = (const float*)d_in[3];
    const float* Wv = (const float*)d_in[4];
    const float* bv = (const float*)d_in[5];
    const float* Wo = (const float*)d_in[6];
    const float* bo = (const float*)d_in[7];
    float* out = (float*)d_out;

    float *Qp, *Kp, *Vp, *Op;
    cudaGetSymbolAddress((void**)&Qp, g_Q);
    cudaGetSymbolAddress((void**)&Kp, g_K);
    cudaGetSymbolAddress((void**)&Vp, g_V);
    cudaGetSymbolAddress((void**)&Op, g_O);

    cudaFuncSetAttribute(attn_kernel,
                         cudaFuncAttributeMaxDynamicSharedMemorySize, 69632);

    dim3 blk(16, 16);
    dim3 gproj(HID / 128, MROWS / 128);   // (6, 64)

    sgemm_nt<<<gproj, blk>>>(x, Wq, nullptr, Qp, MROWS, HID, HID);
    sgemm_nt<<<gproj, blk>>>(x, Wk, nullptr, Kp, MROWS, HID, HID);
    sgemm_nt<<<gproj, blk>>>(x, Wv, bv,      Vp, MROWS, HID, HID);

    attn_kernel<<<dim3(SEQ / 64, NHEAD, BATCH), blk, 69632>>>(Qp, Kp, Vp, eb, Op);

    sgemm_nt<<<gproj, blk>>>(Op, Wo, bo, out, MROWS, HID, HID);
}

// round 4
// speedup vs baseline: 1.5857x; 1.5857x over previous
#include <cuda_runtime.h>

#define BATCH 16
#define SEQ   512
#define HID   768
#define NHEAD 12
#define HD    64
#define MROWS (BATCH*SEQ)   /* 8192 */
#define ATT_SCALE 0.03608439182435161f  /* 768^-0.5 */

// Scratch (module-load allocated, allowed)
__device__ float g_Q[MROWS*HID];
__device__ float g_K[MROWS*HID];
__device__ float g_V[MROWS*HID];
__device__ float g_O[MROWS*HID];

// ---------------------------------------------------------------------------
// tf32 round-to-nearest (unbiased; truncation would bias dot products ~2^-10)
// ---------------------------------------------------------------------------
__device__ __forceinline__ unsigned f2tf32(float x) {
    unsigned r;
    asm("cvt.rna.tf32.f32 %0, %1;" : "=r"(r) : "f"(x));
    return r;
}

__device__ __forceinline__ void mma_tf32(
    float& c0, float& c1, float& c2, float& c3,
    unsigned a0, unsigned a1, unsigned a2, unsigned a3,
    unsigned b0, unsigned b1)
{
    asm volatile(
        "mma.sync.aligned.m16n8k8.row.col.f32.tf32.tf32.f32 "
        "{%0,%1,%2,%3}, {%4,%5,%6,%7}, {%8,%9}, {%0,%1,%2,%3};\n"
        : "+f"(c0), "+f"(c1), "+f"(c2), "+f"(c3)
        : "r"(a0), "r"(a1), "r"(a2), "r"(a3), "r"(b0), "r"(b1));
}

// ---------------------------------------------------------------------------
// C[M x Nout] = A[M x K] @ W[Nout x K]^T (+ bias), tf32 tensor-core GEMM.
// Block tile 128x128, BK=32, 256 threads (8 warps as 2(M) x 4(N)),
// warp tile 64x32 = 4x4 m16n8k8 mmas per k-step.
// smem k-major [k][m] with +8 pad -> conflict-free fragment LDS.
// ---------------------------------------------------------------------------
__global__ __launch_bounds__(256) void gemm_tf32(
    const float* __restrict__ A, const float* __restrict__ W,
    const float* __restrict__ bias, float* __restrict__ C,
    int M, int Nout, int K)
{
    __shared__ float As[32][136];
    __shared__ float Bs[32][136];

    const int tid  = threadIdx.x;
    const int warp = tid >> 5;
    const int lane = tid & 31;
    const int g = lane >> 2;        // 0..7
    const int t = lane & 3;         // 0..3
    const int wm = warp >> 2;       // 0..1  (64-row slab)
    const int wn = warp & 3;        // 0..3  (32-col slab)

    const int lrow = tid >> 2;          // 0..63
    const int lc   = (tid & 3) << 2;    // 0,4,8,12

    const float* Ab = A + (size_t)blockIdx.y * 128 * K;
    const float* Wb = W + (size_t)blockIdx.x * 128 * K;

    float c[4][4][4];
#pragma unroll
    for (int mi = 0; mi < 4; mi++)
#pragma unroll
        for (int nj = 0; nj < 4; nj++)
#pragma unroll
            for (int e = 0; e < 4; e++) c[mi][nj][e] = 0.f;

    for (int kt = 0; kt < K; kt += 32) {
        // gmem prefetch into regs: rows {lrow, lrow+64} x kofs {lc, lc+16}
        float4 ra[2][2], rb[2][2];
#pragma unroll
        for (int r = 0; r < 2; r++)
#pragma unroll
            for (int kq = 0; kq < 2; kq++) {
                ra[r][kq] = *(const float4*)(Ab + (size_t)(lrow + r * 64) * K + kt + lc + kq * 16);
                rb[r][kq] = *(const float4*)(Wb + (size_t)(lrow + r * 64) * K + kt + lc + kq * 16);
            }
        __syncthreads();
#pragma unroll
        for (int r = 0; r < 2; r++)
#pragma unroll
            for (int kq = 0; kq < 2; kq++) {
                const int rr = lrow + r * 64;
                const int kb = lc + kq * 16;
                As[kb + 0][rr] = __uint_as_float(f2tf32(ra[r][kq].x));
                As[kb + 1][rr] = __uint_as_float(f2tf32(ra[r][kq].y));
                As[kb + 2][rr] = __uint_as_float(f2tf32(ra[r][kq].z));
                As[kb + 3][rr] = __uint_as_float(f2tf32(ra[r][kq].w));
                Bs[kb + 0][rr] = __uint_as_float(f2tf32(rb[r][kq].x));
                Bs[kb + 1][rr] = __uint_as_float(f2tf32(rb[r][kq].y));
                Bs[kb + 2][rr] = __uint_as_float(f2tf32(rb[r][kq].z));
                Bs[kb + 3][rr] = __uint_as_float(f2tf32(rb[r][kq].w));
            }
        __syncthreads();

#pragma unroll
        for (int ks = 0; ks < 4; ks++) {
            const int kb = ks * 8;
            unsigned af[4][4], bf[4][2];
#pragma unroll
            for (int mi = 0; mi < 4; mi++) {
                const int r = wm * 64 + mi * 16 + g;
                af[mi][0] = __float_as_uint(As[kb + t    ][r]);
                af[mi][1] = __float_as_uint(As[kb + t    ][r + 8]);
                af[mi][2] = __float_as_uint(As[kb + t + 4][r]);
                af[mi][3] = __float_as_uint(As[kb + t + 4][r + 8]);
            }
#pragma unroll
            for (int nj = 0; nj < 4; nj++) {
                const int cc = wn * 32 + nj * 8 + g;
                bf[nj][0] = __float_as_uint(Bs[kb + t    ][cc]);
                bf[nj][1] = __float_as_uint(Bs[kb + t + 4][cc]);
            }
#pragma unroll
            for (int mi = 0; mi < 4; mi++)
#pragma unroll
                for (int nj = 0; nj < 4; nj++)
                    mma_tf32(c[mi][nj][0], c[mi][nj][1], c[mi][nj][2], c[mi][nj][3],
                             af[mi][0], af[mi][1], af[mi][2], af[mi][3],
                             bf[nj][0], bf[nj][1]);
        }
    }

    // epilogue: c0,c1 -> (row g, cols 2t,2t+1); c2,c3 -> (row g+8)
    const int row_base = blockIdx.y * 128 + wm * 64;
    const int col_base = blockIdx.x * 128 + wn * 32;
#pragma unroll
    for (int mi = 0; mi < 4; mi++) {
#pragma unroll
        for (int nj = 0; nj < 4; nj++) {
            const int col = col_base + nj * 8 + 2 * t;
            float b0 = 0.f, b1 = 0.f;
            if (bias) { b0 = bias[col]; b1 = bias[col + 1]; }
            const int r0 = row_base + mi * 16 + g;
            float2 v0 = make_float2(c[mi][nj][0] + b0, c[mi][nj][1] + b1);
            float2 v1 = make_float2(c[mi][nj][2] + b0, c[mi][nj][3] + b1);
            *(float2*)(C + (size_t)r0 * Nout + col) = v0;
            *(float2*)(C + (size_t)(r0 + 8) * Nout + col) = v1;
        }
    }
}

// ---------------------------------------------------------------------------
// Flash attention with additive bias (unchanged from R2 — R4 target).
// Block: 64 query rows of one (b,h). 16x16 threads, 4x4 per-thread tiles.
// ---------------------------------------------------------------------------
__global__ __launch_bounds__(256) void attn_kernel(
    const float* __restrict__ Q, const float* __restrict__ K,
    const float* __restrict__ V, const float* __restrict__ bias,
    float* __restrict__ O)
{
    extern __shared__ float sm[];
    float* q_sT = sm;                 // [d][row]
    float* k_sT = sm + 64 * 68;       // [d][col]
    float* v_s  = sm + 2 * 64 * 68;   // [col][d]
    float* p_sT = sm + 3 * 64 * 68;   // [col][row]

    const int b = blockIdx.z, h = blockIdx.y;
    const int n0 = blockIdx.x * 64;
    const int tx = threadIdx.x, ty = threadIdx.y;
    const int tid = ty * 16 + tx;
    const int dl = tid & 63;          // 0..63
    const int rl = tid >> 6;          // 0..3

    {
        const float* qb = Q + ((size_t)(b * SEQ + n0)) * HID + h * HD;
#pragma unroll
        for (int rr = rl; rr < 64; rr += 4)
            q_sT[dl * 68 + rr] = qb[rr * HID + dl];
    }

    float m_i[4], l_i[4], acc[4][4];
#pragma unroll
    for (int i = 0; i < 4; i++) {
        m_i[i] = -1e30f; l_i[i] = 0.f;
#pragma unroll
        for (int j = 0; j < 4; j++) acc[i][j] = 0.f;
    }

    for (int mt = 0; mt < 8; mt++) {
        const int m0 = mt * 64;
        __syncthreads();
        {
            const float* kb = K + ((size_t)(b * SEQ + m0)) * HID + h * HD;
            const float* vb = V + ((size_t)(b * SEQ + m0)) * HID + h * HD;
#pragma unroll
            for (int cc = rl; cc < 64; cc += 4) {
                k_sT[dl * 68 + cc] = kb[cc * HID + dl];
                v_s[cc * 68 + dl]  = vb[cc * HID + dl];
            }
        }
        __syncthreads();

        float s[4][4];
#pragma unroll
        for (int i = 0; i < 4; i++)
#pragma unroll
            for (int j = 0; j < 4; j++) s[i][j] = 0.f;
#pragma unroll 16
        for (int kk = 0; kk < 64; kk++) {
            float4 a = *(const float4*)&q_sT[kk * 68 + ty * 4];
            float4 kf = *(const float4*)&k_sT[kk * 68 + tx * 4];
            float af[4] = {a.x, a.y, a.z, a.w};
            float bf[4] = {kf.x, kf.y, kf.z, kf.w};
#pragma unroll
            for (int i = 0; i < 4; i++)
#pragma unroll
                for (int j = 0; j < 4; j++) s[i][j] += af[i] * bf[j];
        }
#pragma unroll
        for (int i = 0; i < 4; i++) {
            float4 bb = *(const float4*)(bias +
                ((size_t)(b * SEQ + n0 + ty * 4 + i)) * SEQ + m0 + tx * 4);
            s[i][0] = s[i][0] * ATT_SCALE + bb.x;
            s[i][1] = s[i][1] * ATT_SCALE + bb.y;
            s[i][2] = s[i][2] * ATT_SCALE + bb.z;
            s[i][3] = s[i][3] * ATT_SCALE + bb.w;
        }
#pragma unroll
        for (int i = 0; i < 4; i++) {
            float tm = fmaxf(fmaxf(s[i][0], s[i][1]), fmaxf(s[i][2], s[i][3]));
#pragma unroll
            for (int off = 8; off > 0; off >>= 1)
                tm = fmaxf(tm, __shfl_xor_sync(0xffffffffu, tm, off));
            float mn = fmaxf(m_i[i], tm);
            float p0 = __expf(s[i][0] - mn);
            float p1 = __expf(s[i][1] - mn);
            float p2 = __expf(s[i][2] - mn);
            float p3 = __expf(s[i][3] - mn);
            float rs = (p0 + p1) + (p2 + p3);
#pragma unroll
            for (int off = 8; off > 0; off >>= 1)
                rs += __shfl_xor_sync(0xffffffffu, rs, off);
            float al = __expf(m_i[i] - mn);
            l_i[i] = l_i[i] * al + rs;
            m_i[i] = mn;
            acc[i][0] *= al; acc[i][1] *= al; acc[i][2] *= al; acc[i][3] *= al;
            p_sT[(tx * 4 + 0) * 68 + ty * 4 + i] = p0;
            p_sT[(tx * 4 + 1) * 68 + ty * 4 + i] = p1;
            p_sT[(tx * 4 + 2) * 68 + ty * 4 + i] = p2;
            p_sT[(tx * 4 + 3) * 68 + ty * 4 + i] = p3;
        }
        __syncthreads();
#pragma unroll 8
        for (int cc = 0; cc < 64; cc++) {
            float4 pa = *(const float4*)&p_sT[cc * 68 + ty * 4];
            float4 vv = *(const float4*)&v_s[cc * 68 + tx * 4];
            float pf[4] = {pa.x, pa.y, pa.z, pa.w};
            float vf[4] = {vv.x, vv.y, vv.z, vv.w};
#pragma unroll
            for (int i = 0; i < 4; i++)
#pragma unroll
                for (int j = 0; j < 4; j++) acc[i][j] += pf[i] * vf[j];
        }
    }

    float* ob = O + ((size_t)(b * SEQ + n0 + ty * 4)) * HID + h * HD + tx * 4;
#pragma unroll
    for (int i = 0; i < 4; i++) {
        float inv = 1.0f / l_i[i];
        float4 r = make_float4(acc[i][0] * inv, acc[i][1] * inv,
                               acc[i][2] * inv, acc[i][3] * inv);
        *(float4*)(ob + (size_t)i * HID) = r;
    }
}

// ---------------------------------------------------------------------------
extern "C" void kernel_launch(void* const* d_in, const int* in_sizes, int n_in,
                              void* d_out, int out_size)
{
    const float* x  = (const float*)d_in[0];
    const float* eb = (const float*)d_in[1];
    const float* Wq = (const float*)d_in[2];
    const float* Wk = (const float*)d_in[3];
    const float* Wv = (const float*)d_in[4];
    const float* bv = (const float*)d_in[5];
    const float* Wo = (const float*)d_in[6];
    const float* bo = (const float*)d_in[7];
    float* out = (float*)d_out;

    float *Qp, *Kp, *Vp, *Op;
    cudaGetSymbolAddress((void**)&Qp, g_Q);
    cudaGetSymbolAddress((void**)&Kp, g_K);
    cudaGetSymbolAddress((void**)&Vp, g_V);
    cudaGetSymbolAddress((void**)&Op, g_O);

    cudaFuncSetAttribute(attn_kernel,
                         cudaFuncAttributeMaxDynamicSharedMemorySize, 69632);

    dim3 gproj(HID / 128, MROWS / 128);   // (6, 64)

    gemm_tf32<<<gproj, 256>>>(x, Wq, nullptr, Qp, MROWS, HID, HID);
    gemm_tf32<<<gproj, 256>>>(x, Wk, nullptr, Kp, MROWS, HID, HID);
    gemm_tf32<<<gproj, 256>>>(x, Wv, bv,      Vp, MROWS, HID, HID);

    attn_kernel<<<dim3(SEQ / 64, NHEAD, BATCH), dim3(16, 16), 69632>>>(Qp, Kp, Vp, eb, Op);

    gemm_tf32<<<gproj, 256>>>(Op, Wo, bo, out, MROWS, HID, HID);
}

// round 5
// speedup vs baseline: 2.1207x; 1.3374x over previous
#include <cuda_runtime.h>

#define BATCH 16
#define SEQ   512
#define HID   768
#define NHEAD 12
#define HD    64
#define MROWS (BATCH*SEQ)   /* 8192 */
#define ATT_SCALE 0.03608439182435161f  /* 768^-0.5 */

// Scratch (module-load allocated, allowed)
__device__ float g_Q[MROWS*HID];
__device__ float g_K[MROWS*HID];
__device__ float g_V[MROWS*HID];
__device__ float g_O[MROWS*HID];

// ---------------------------------------------------------------------------
// tf32 round-to-nearest (unbiased)
// ---------------------------------------------------------------------------
__device__ __forceinline__ unsigned f2tf32(float x) {
    unsigned r;
    asm("cvt.rna.tf32.f32 %0, %1;" : "=r"(r) : "f"(x));
    return r;
}

__device__ __forceinline__ void mma_tf32(
    float& c0, float& c1, float& c2, float& c3,
    unsigned a0, unsigned a1, unsigned a2, unsigned a3,
    unsigned b0, unsigned b1)
{
    asm volatile(
        "mma.sync.aligned.m16n8k8.row.col.f32.tf32.tf32.f32 "
        "{%0,%1,%2,%3}, {%4,%5,%6,%7}, {%8,%9}, {%0,%1,%2,%3};\n"
        : "+f"(c0), "+f"(c1), "+f"(c2), "+f"(c3)
        : "r"(a0), "r"(a1), "r"(a2), "r"(a3), "r"(b0), "r"(b1));
}

// ---------------------------------------------------------------------------
// C[M x Nout] = A[M x K] @ W[Nout x K]^T (+ bias), tf32 tensor-core GEMM.
// (unchanged from R3)
// ---------------------------------------------------------------------------
__global__ __launch_bounds__(256) void gemm_tf32(
    const float* __restrict__ A, const float* __restrict__ W,
    const float* __restrict__ bias, float* __restrict__ C,
    int M, int Nout, int K)
{
    __shared__ float As[32][136];
    __shared__ float Bs[32][136];

    const int tid  = threadIdx.x;
    const int warp = tid >> 5;
    const int lane = tid & 31;
    const int g = lane >> 2;
    const int t = lane & 3;
    const int wm = warp >> 2;
    const int wn = warp & 3;

    const int lrow = tid >> 2;
    const int lc   = (tid & 3) << 2;

    const float* Ab = A + (size_t)blockIdx.y * 128 * K;
    const float* Wb = W + (size_t)blockIdx.x * 128 * K;

    float c[4][4][4];
#pragma unroll
    for (int mi = 0; mi < 4; mi++)
#pragma unroll
        for (int nj = 0; nj < 4; nj++)
#pragma unroll
            for (int e = 0; e < 4; e++) c[mi][nj][e] = 0.f;

    for (int kt = 0; kt < K; kt += 32) {
        float4 ra[2][2], rb[2][2];
#pragma unroll
        for (int r = 0; r < 2; r++)
#pragma unroll
            for (int kq = 0; kq < 2; kq++) {
                ra[r][kq] = *(const float4*)(Ab + (size_t)(lrow + r * 64) * K + kt + lc + kq * 16);
                rb[r][kq] = *(const float4*)(Wb + (size_t)(lrow + r * 64) * K + kt + lc + kq * 16);
            }
        __syncthreads();
#pragma unroll
        for (int r = 0; r < 2; r++)
#pragma unroll
            for (int kq = 0; kq < 2; kq++) {
                const int rr = lrow + r * 64;
                const int kb = lc + kq * 16;
                As[kb + 0][rr] = __uint_as_float(f2tf32(ra[r][kq].x));
                As[kb + 1][rr] = __uint_as_float(f2tf32(ra[r][kq].y));
                As[kb + 2][rr] = __uint_as_float(f2tf32(ra[r][kq].z));
                As[kb + 3][rr] = __uint_as_float(f2tf32(ra[r][kq].w));
                Bs[kb + 0][rr] = __uint_as_float(f2tf32(rb[r][kq].x));
                Bs[kb + 1][rr] = __uint_as_float(f2tf32(rb[r][kq].y));
                Bs[kb + 2][rr] = __uint_as_float(f2tf32(rb[r][kq].z));
                Bs[kb + 3][rr] = __uint_as_float(f2tf32(rb[r][kq].w));
            }
        __syncthreads();

#pragma unroll
        for (int ks = 0; ks < 4; ks++) {
            const int kb = ks * 8;
            unsigned af[4][4], bf[4][2];
#pragma unroll
            for (int mi = 0; mi < 4; mi++) {
                const int r = wm * 64 + mi * 16 + g;
                af[mi][0] = __float_as_uint(As[kb + t    ][r]);
                af[mi][1] = __float_as_uint(As[kb + t    ][r + 8]);
                af[mi][2] = __float_as_uint(As[kb + t + 4][r]);
                af[mi][3] = __float_as_uint(As[kb + t + 4][r + 8]);
            }
#pragma unroll
            for (int nj = 0; nj < 4; nj++) {
                const int cc = wn * 32 + nj * 8 + g;
                bf[nj][0] = __float_as_uint(Bs[kb + t    ][cc]);
                bf[nj][1] = __float_as_uint(Bs[kb + t + 4][cc]);
            }
#pragma unroll
            for (int mi = 0; mi < 4; mi++)
#pragma unroll
                for (int nj = 0; nj < 4; nj++)
                    mma_tf32(c[mi][nj][0], c[mi][nj][1], c[mi][nj][2], c[mi][nj][3],
                             af[mi][0], af[mi][1], af[mi][2], af[mi][3],
                             bf[nj][0], bf[nj][1]);
        }
    }

    const int row_base = blockIdx.y * 128 + wm * 64;
    const int col_base = blockIdx.x * 128 + wn * 32;
#pragma unroll
    for (int mi = 0; mi < 4; mi++) {
#pragma unroll
        for (int nj = 0; nj < 4; nj++) {
            const int col = col_base + nj * 8 + 2 * t;
            float b0 = 0.f, b1 = 0.f;
            if (bias) { b0 = bias[col]; b1 = bias[col + 1]; }
            const int r0 = row_base + mi * 16 + g;
            float2 v0 = make_float2(c[mi][nj][0] + b0, c[mi][nj][1] + b1);
            float2 v1 = make_float2(c[mi][nj][2] + b0, c[mi][nj][3] + b1);
            *(float2*)(C + (size_t)r0 * Nout + col) = v0;
            *(float2*)(C + (size_t)(r0 + 8) * Nout + col) = v1;
        }
    }
}

// ---------------------------------------------------------------------------
// Flash attention on tf32 tensor cores.
// Block = 64 Q-rows of one (b,h); 4 warps, warp owns 16 rows.
// smem: Qs[d=64][68], Ks[d=64][68], Vs[m=64][68], Ps[4 warps][m=64][24]
// dyn smem = (3*64*68 + 4*64*24)*4 = 76800 B
// ---------------------------------------------------------------------------
#define QS_OFF 0
#define KS_OFF (64*68)
#define VS_OFF (2*64*68)
#define PS_OFF (3*64*68)
#define ATTN_SMEM ((3*64*68 + 4*64*24)*4)

__global__ __launch_bounds__(128) void attn_mma(
    const float* __restrict__ Q, const float* __restrict__ K,
    const float* __restrict__ V, const float* __restrict__ bias,
    float* __restrict__ O)
{
    extern __shared__ float sm[];
    float* Qs = sm + QS_OFF;
    float* Ks = sm + KS_OFF;
    float* Vs = sm + VS_OFF;

    const int b = blockIdx.z, h = blockIdx.y;
    const int n0 = blockIdx.x * 64;
    const int tid  = threadIdx.x;
    const int warp = tid >> 5;
    const int lane = tid & 31;
    const int g = lane >> 2;       // 0..7
    const int t = lane & 3;        // 0..3
    const int r0 = warp * 16;      // warp's local q-row base
    float* Psw = sm + PS_OFF + warp * 64 * 24;

    const int dl = tid & 63;       // 0..63 (d / col lane)
    const int rl = tid >> 6;       // 0..1

    // --- load Q tile transposed -> Qs[d][row], tf32 ---
    {
        const float* qb = Q + ((size_t)(b * SEQ + n0)) * HID + h * HD;
#pragma unroll
        for (int rr = rl; rr < 64; rr += 2)
            Qs[dl * 68 + rr] = __uint_as_float(f2tf32(qb[rr * HID + dl]));
    }

    float m_st[2], l_st[2];
    m_st[0] = m_st[1] = -1e30f;
    l_st[0] = l_st[1] = 0.f;
    float o[8][4];
#pragma unroll
    for (int nb = 0; nb < 8; nb++)
#pragma unroll
        for (int e = 0; e < 4; e++) o[nb][e] = 0.f;

    const int qra = b * SEQ + n0 + r0 + g;       // global q row (low)
    const float* bias_ra = bias + (size_t)qra * SEQ;
    const float* bias_rb = bias_ra + (size_t)8 * SEQ;

    for (int mt = 0; mt < 8; mt++) {
        const int m0 = mt * 64;
        __syncthreads();   // previous-iter smem reads complete
        {
            const float* kb = K + ((size_t)(b * SEQ + m0)) * HID + h * HD;
            const float* vb = V + ((size_t)(b * SEQ + m0)) * HID + h * HD;
#pragma unroll
            for (int cc = rl; cc < 64; cc += 2) {
                Ks[dl * 68 + cc] = __uint_as_float(f2tf32(kb[cc * HID + dl]));
                Vs[cc * 68 + dl] = __uint_as_float(f2tf32(vb[cc * HID + dl]));
            }
        }
        __syncthreads();

        // --- S = Q K^T : warp computes 16x64 ---
        float s[8][4];
#pragma unroll
        for (int nb = 0; nb < 8; nb++)
#pragma unroll
            for (int e = 0; e < 4; e++) s[nb][e] = 0.f;
#pragma unroll
        for (int ks = 0; ks < 8; ks++) {
            const int kb = ks * 8;
            unsigned a0 = __float_as_uint(Qs[(kb + t    ) * 68 + r0 + g    ]);
            unsigned a1 = __float_as_uint(Qs[(kb + t    ) * 68 + r0 + g + 8]);
            unsigned a2 = __float_as_uint(Qs[(kb + t + 4) * 68 + r0 + g    ]);
            unsigned a3 = __float_as_uint(Qs[(kb + t + 4) * 68 + r0 + g + 8]);
#pragma unroll
            for (int nb = 0; nb < 8; nb++) {
                unsigned b0 = __float_as_uint(Ks[(kb + t    ) * 68 + nb * 8 + g]);
                unsigned b1 = __float_as_uint(Ks[(kb + t + 4) * 68 + nb * 8 + g]);
                mma_tf32(s[nb][0], s[nb][1], s[nb][2], s[nb][3], a0, a1, a2, a3, b0, b1);
            }
        }

        // --- scale + bias ---
#pragma unroll
        for (int nb = 0; nb < 8; nb++) {
            float2 ba = *(const float2*)(bias_ra + m0 + nb * 8 + 2 * t);
            float2 bb = *(const float2*)(bias_rb + m0 + nb * 8 + 2 * t);
            s[nb][0] = s[nb][0] * ATT_SCALE + ba.x;
            s[nb][1] = s[nb][1] * ATT_SCALE + ba.y;
            s[nb][2] = s[nb][2] * ATT_SCALE + bb.x;
            s[nb][3] = s[nb][3] * ATT_SCALE + bb.y;
        }

        // --- online softmax: rows g (elems 0,1) and g+8 (elems 2,3) ---
        float tm0 = -1e30f, tm1 = -1e30f;
#pragma unroll
        for (int nb = 0; nb < 8; nb++) {
            tm0 = fmaxf(tm0, fmaxf(s[nb][0], s[nb][1]));
            tm1 = fmaxf(tm1, fmaxf(s[nb][2], s[nb][3]));
        }
        tm0 = fmaxf(tm0, __shfl_xor_sync(0xffffffffu, tm0, 1));
        tm0 = fmaxf(tm0, __shfl_xor_sync(0xffffffffu, tm0, 2));
        tm1 = fmaxf(tm1, __shfl_xor_sync(0xffffffffu, tm1, 1));
        tm1 = fmaxf(tm1, __shfl_xor_sync(0xffffffffu, tm1, 2));
        const float mn0 = fmaxf(m_st[0], tm0);
        const float mn1 = fmaxf(m_st[1], tm1);

        float ls0 = 0.f, ls1 = 0.f;
#pragma unroll
        for (int nb = 0; nb < 8; nb++) {
            float p0 = __expf(s[nb][0] - mn0);
            float p1 = __expf(s[nb][1] - mn0);
            float p2 = __expf(s[nb][2] - mn1);
            float p3 = __expf(s[nb][3] - mn1);
            ls0 += p0 + p1;
            ls1 += p2 + p3;
            const int col = nb * 8 + 2 * t;
            Psw[(col    ) * 24 + g    ] = __uint_as_float(f2tf32(p0));
            Psw[(col + 1) * 24 + g    ] = __uint_as_float(f2tf32(p1));
            Psw[(col    ) * 24 + g + 8] = __uint_as_float(f2tf32(p2));
            Psw[(col + 1) * 24 + g + 8] = __uint_as_float(f2tf32(p3));
        }
        ls0 += __shfl_xor_sync(0xffffffffu, ls0, 1);
        ls0 += __shfl_xor_sync(0xffffffffu, ls0, 2);
        ls1 += __shfl_xor_sync(0xffffffffu, ls1, 1);
        ls1 += __shfl_xor_sync(0xffffffffu, ls1, 2);

        const float al0 = __expf(m_st[0] - mn0);
        const float al1 = __expf(m_st[1] - mn1);
        l_st[0] = l_st[0] * al0 + ls0;
        l_st[1] = l_st[1] * al1 + ls1;
        m_st[0] = mn0; m_st[1] = mn1;
#pragma unroll
        for (int nb = 0; nb < 8; nb++) {
            o[nb][0] *= al0; o[nb][1] *= al0;
            o[nb][2] *= al1; o[nb][3] *= al1;
        }
        __syncwarp();   // Psw visible to this warp's mma

        // --- O += P V : 16x64 += 16x64 @ 64x64 ---
#pragma unroll
        for (int ks = 0; ks < 8; ks++) {
            const int kb = ks * 8;
            unsigned a0 = __float_as_uint(Psw[(kb + t    ) * 24 + g    ]);
            unsigned a1 = __float_as_uint(Psw[(kb + t    ) * 24 + g + 8]);
            unsigned a2 = __float_as_uint(Psw[(kb + t + 4) * 24 + g    ]);
            unsigned a3 = __float_as_uint(Psw[(kb + t + 4) * 24 + g + 8]);
#pragma unroll
            for (int nb = 0; nb < 8; nb++) {
                unsigned b0 = __float_as_uint(Vs[(kb + t    ) * 68 + nb * 8 + g]);
                unsigned b1 = __float_as_uint(Vs[(kb + t + 4) * 68 + nb * 8 + g]);
                mma_tf32(o[nb][0], o[nb][1], o[nb][2], o[nb][3], a0, a1, a2, a3, b0, b1);
            }
        }
    }

    // --- epilogue: normalize and store ---
    const float inv0 = 1.0f / l_st[0];
    const float inv1 = 1.0f / l_st[1];
    float* oa = O + (size_t)qra * HID + h * HD;
    float* ob = oa + (size_t)8 * HID;
#pragma unroll
    for (int nb = 0; nb < 8; nb++) {
        const int col = nb * 8 + 2 * t;
        *(float2*)(oa + col) = make_float2(o[nb][0] * inv0, o[nb][1] * inv0);
        *(float2*)(ob + col) = make_float2(o[nb][2] * inv1, o[nb][3] * inv1);
    }
}

// ---------------------------------------------------------------------------
extern "C" void kernel_launch(void* const* d_in, const int* in_sizes, int n_in,
                              void* d_out, int out_size)
{
    const float* x  = (const float*)d_in[0];
    const float* eb = (const float*)d_in[1];
    const float* Wq = (const float*)d_in[2];
    const float* Wk = (const float*)d_in[3];
    const float* Wv = (const float*)d_in[4];
    const float* bv = (const float*)d_in[5];
    const float* Wo = (const float*)d_in[6];
    const float* bo = (const float*)d_in[7];
    float* out = (float*)d_out;

    float *Qp, *Kp, *Vp, *Op;
    cudaGetSymbolAddress((void**)&Qp, g_Q);
    cudaGetSymbolAddress((void**)&Kp, g_K);
    cudaGetSymbolAddress((void**)&Vp, g_V);
    cudaGetSymbolAddress((void**)&Op, g_O);

    cudaFuncSetAttribute(attn_mma,
                         cudaFuncAttributeMaxDynamicSharedMemorySize, ATTN_SMEM);

    dim3 gproj(HID / 128, MROWS / 128);   // (6, 64)

    gemm_tf32<<<gproj, 256>>>(x, Wq, nullptr, Qp, MROWS, HID, HID);
    gemm_tf32<<<gproj, 256>>>(x, Wk, nullptr, Kp, MROWS, HID, HID);
    gemm_tf32<<<gproj, 256>>>(x, Wv, bv,      Vp, MROWS, HID, HID);

    attn_mma<<<dim3(SEQ / 64, NHEAD, BATCH), 128, ATTN_SMEM>>>(Qp, Kp, Vp, eb, Op);

    gemm_tf32<<<gproj, 256>>>(Op, Wo, bo, out, MROWS, HID, HID);
}

// round 7
// speedup vs baseline: 2.3683x; 1.1167x over previous
#include <cuda_runtime.h>

#define BATCH 16
#define SEQ   512
#define HID   768
#define NHEAD 12
#define HD    64
#define MROWS (BATCH*SEQ)   /* 8192 */
#define ATT_SCALE 0.03608439182435161f  /* 768^-0.5 */

// Scratch (module-load allocated, allowed)
__device__ float g_Q[MROWS*HID];
__device__ float g_K[MROWS*HID];
__device__ float g_V[MROWS*HID];
__device__ float g_O[MROWS*HID];

// ---------------------------------------------------------------------------
__device__ __forceinline__ unsigned f2tf32(float x) {
    unsigned r;
    asm("cvt.rna.tf32.f32 %0, %1;" : "=r"(r) : "f"(x));
    return r;
}

__device__ __forceinline__ void mma_tf32(
    float& c0, float& c1, float& c2, float& c3,
    unsigned a0, unsigned a1, unsigned a2, unsigned a3,
    unsigned b0, unsigned b1)
{
    asm volatile(
        "mma.sync.aligned.m16n8k8.row.col.f32.tf32.tf32.f32 "
        "{%0,%1,%2,%3}, {%4,%5,%6,%7}, {%8,%9}, {%0,%1,%2,%3};\n"
        : "+f"(c0), "+f"(c1), "+f"(c2), "+f"(c3)
        : "r"(a0), "r"(a1), "r"(a2), "r"(a3), "r"(b0), "r"(b1));
}

// ---------------------------------------------------------------------------
// tf32 GEMM body: C[M x 768] = A[M x 768] @ W[768 x 768]^T (+ bias)
// Block tile 128x128, BK=32, 256 threads, warp tile 64x32.
// Double-buffered smem (dynamic, 69632 B) + register prefetch of next K-tile;
// ONE __syncthreads per K-iteration.
// ---------------------------------------------------------------------------
#define GK 768
#define GNK (GK/32)          /* 24 */
#define ASTR (32*136)        /* floats per buffer */
#define GEMM_SMEM (4*ASTR*4) /* 69632 B */

__device__ __forceinline__ void gemm_body(
    const float* __restrict__ A, const float* __restrict__ W,
    const float* __restrict__ bias, float* __restrict__ C,
    int bx, int by)
{
    extern __shared__ float smb[];

    const int tid  = threadIdx.x;
    const int warp = tid >> 5;
    const int lane = tid & 31;
    const int g = lane >> 2;
    const int t = lane & 3;
    const int wm = warp >> 2;
    const int wn = warp & 3;

    const int lrow = tid >> 2;
    const int lc   = (tid & 3) << 2;

    const float* Ab = A + (size_t)by * 128 * GK;
    const float* Wb = W + (size_t)bx * 128 * GK;

    float c[4][4][4];
#pragma unroll
    for (int mi = 0; mi < 4; mi++)
#pragma unroll
        for (int nj = 0; nj < 4; nj++)
#pragma unroll
            for (int e = 0; e < 4; e++) c[mi][nj][e] = 0.f;

    float4 ra[2][2], rb[2][2];
    // preload K-tile 0
#pragma unroll
    for (int r = 0; r < 2; r++)
#pragma unroll
        for (int kq = 0; kq < 2; kq++) {
            ra[r][kq] = *(const float4*)(Ab + (size_t)(lrow + r * 64) * GK + lc + kq * 16);
            rb[r][kq] = *(const float4*)(Wb + (size_t)(lrow + r * 64) * GK + lc + kq * 16);
        }

    int buf = 0;
    for (int it = 0; it < GNK; it++) {
        float* Asb = smb + buf * ASTR;
        float* Bsb = smb + 2 * ASTR + buf * ASTR;
        // store prefetched regs -> smem[buf] (tf32 converted, k-major)
#pragma unroll
        for (int r = 0; r < 2; r++)
#pragma unroll
            for (int kq = 0; kq < 2; kq++) {
                const int rr = lrow + r * 64;
                float* as = Asb + (lc + kq * 16) * 136 + rr;
                float* bs = Bsb + (lc + kq * 16) * 136 + rr;
                as[0 * 136] = __uint_as_float(f2tf32(ra[r][kq].x));
                as[1 * 136] = __uint_as_float(f2tf32(ra[r][kq].y));
                as[2 * 136] = __uint_as_float(f2tf32(ra[r][kq].z));
                as[3 * 136] = __uint_as_float(f2tf32(ra[r][kq].w));
                bs[0 * 136] = __uint_as_float(f2tf32(rb[r][kq].x));
                bs[1 * 136] = __uint_as_float(f2tf32(rb[r][kq].y));
                bs[2 * 136] = __uint_as_float(f2tf32(rb[r][kq].z));
                bs[3 * 136] = __uint_as_float(f2tf32(rb[r][kq].w));
            }
        __syncthreads();

        // issue gmem loads for next K-tile (latency hidden behind mma loop)
        if (it + 1 < GNK) {
            const int kt = (it + 1) * 32;
#pragma unroll
            for (int r = 0; r < 2; r++)
#pragma unroll
                for (int kq = 0; kq < 2; kq++) {
                    ra[r][kq] = *(const float4*)(Ab + (size_t)(lrow + r * 64) * GK + kt + lc + kq * 16);
                    rb[r][kq] = *(const float4*)(Wb + (size_t)(lrow + r * 64) * GK + kt + lc + kq * 16);
                }
        }

        // compute on smem[buf]
#pragma unroll
        for (int ks = 0; ks < 4; ks++) {
            const int kb = ks * 8;
            unsigned af[4][4], bf[4][2];
#pragma unroll
            for (int mi = 0; mi < 4; mi++) {
                const int r = wm * 64 + mi * 16 + g;
                af[mi][0] = __float_as_uint(Asb[(kb + t    ) * 136 + r]);
                af[mi][1] = __float_as_uint(Asb[(kb + t    ) * 136 + r + 8]);
                af[mi][2] = __float_as_uint(Asb[(kb + t + 4) * 136 + r]);
                af[mi][3] = __float_as_uint(Asb[(kb + t + 4) * 136 + r + 8]);
            }
#pragma unroll
            for (int nj = 0; nj < 4; nj++) {
                const int cc = wn * 32 + nj * 8 + g;
                bf[nj][0] = __float_as_uint(Bsb[(kb + t    ) * 136 + cc]);
                bf[nj][1] = __float_as_uint(Bsb[(kb + t + 4) * 136 + cc]);
            }
#pragma unroll
            for (int mi = 0; mi < 4; mi++)
#pragma unroll
                for (int nj = 0; nj < 4; nj++)
                    mma_tf32(c[mi][nj][0], c[mi][nj][1], c[mi][nj][2], c[mi][nj][3],
                             af[mi][0], af[mi][1], af[mi][2], af[mi][3],
                             bf[nj][0], bf[nj][1]);
        }
        buf ^= 1;
    }

    const int row_base = by * 128 + wm * 64;
    const int col_base = bx * 128 + wn * 32;
#pragma unroll
    for (int mi = 0; mi < 4; mi++) {
#pragma unroll
        for (int nj = 0; nj < 4; nj++) {
            const int col = col_base + nj * 8 + 2 * t;
            float b0 = 0.f, b1 = 0.f;
            if (bias) { b0 = bias[col]; b1 = bias[col + 1]; }
            const int r0 = row_base + mi * 16 + g;
            float2 v0 = make_float2(c[mi][nj][0] + b0, c[mi][nj][1] + b1);
            float2 v1 = make_float2(c[mi][nj][2] + b0, c[mi][nj][3] + b1);
            *(float2*)(C + (size_t)r0 * HID + col) = v0;
            *(float2*)(C + (size_t)(r0 + 8) * HID + col) = v1;
        }
    }
}

// Fused Q/K/V projection: blockIdx.z selects which of the three GEMMs.
__global__ __launch_bounds__(256) void gemm_qkv(
    const float* __restrict__ x,
    const float* __restrict__ Wq, const float* __restrict__ Wk,
    const float* __restrict__ Wv, const float* __restrict__ bv,
    float* __restrict__ Qo, float* __restrict__ Ko, float* __restrict__ Vo)
{
    const int z = blockIdx.z;
    const float* W = (z == 0) ? Wq : (z == 1) ? Wk : Wv;
    float* C = (z == 0) ? Qo : (z == 1) ? Ko : Vo;
    const float* bias = (z == 2) ? bv : nullptr;
    gemm_body(x, W, bias, C, blockIdx.x, blockIdx.y);
}

__global__ __launch_bounds__(256) void gemm_one(
    const float* __restrict__ A, const float* __restrict__ W,
    const float* __restrict__ bias, float* __restrict__ C)
{
    gemm_body(A, W, bias, C, blockIdx.x, blockIdx.y);
}

// ---------------------------------------------------------------------------
// Flash attention on tf32 tensor cores (unchanged from R4).
// ---------------------------------------------------------------------------
#define QS_OFF 0
#define KS_OFF (64*68)
#define VS_OFF (2*64*68)
#define PS_OFF (3*64*68)
#define ATTN_SMEM ((3*64*68 + 4*64*24)*4)

__global__ __launch_bounds__(128) void attn_mma(
    const float* __restrict__ Q, const float* __restrict__ K,
    const float* __restrict__ V, const float* __restrict__ bias,
    float* __restrict__ O)
{
    extern __shared__ float sm[];
    float* Qs = sm + QS_OFF;
    float* Ks = sm + KS_OFF;
    float* Vs = sm + VS_OFF;

    const int b = blockIdx.z, h = blockIdx.y;
    const int n0 = blockIdx.x * 64;
    const int tid  = threadIdx.x;
    const int warp = tid >> 5;
    const int lane = tid & 31;
    const int g = lane >> 2;
    const int t = lane & 3;
    const int r0 = warp * 16;
    float* Psw = sm + PS_OFF + warp * 64 * 24;

    const int dl = tid & 63;
    const int rl = tid >> 6;

    {
        const float* qb = Q + ((size_t)(b * SEQ + n0)) * HID + h * HD;
#pragma unroll
        for (int rr = rl; rr < 64; rr += 2)
            Qs[dl * 68 + rr] = __uint_as_float(f2tf32(qb[rr * HID + dl]));
    }

    float m_st[2], l_st[2];
    m_st[0] = m_st[1] = -1e30f;
    l_st[0] = l_st[1] = 0.f;
    float o[8][4];
#pragma unroll
    for (int nb = 0; nb < 8; nb++)
#pragma unroll
        for (int e = 0; e < 4; e++) o[nb][e] = 0.f;

    const int qra = b * SEQ + n0 + r0 + g;
    const float* bias_ra = bias + (size_t)qra * SEQ;
    const float* bias_rb = bias_ra + (size_t)8 * SEQ;

    for (int mt = 0; mt < 8; mt++) {
        const int m0 = mt * 64;
        __syncthreads();
        {
            const float* kb = K + ((size_t)(b * SEQ + m0)) * HID + h * HD;
            const float* vb = V + ((size_t)(b * SEQ + m0)) * HID + h * HD;
#pragma unroll
            for (int cc = rl; cc < 64; cc += 2) {
                Ks[dl * 68 + cc] = __uint_as_float(f2tf32(kb[cc * HID + dl]));
                Vs[cc * 68 + dl] = __uint_as_float(f2tf32(vb[cc * HID + dl]));
            }
        }
        __syncthreads();

        float s[8][4];
#pragma unroll
        for (int nb = 0; nb < 8; nb++)
#pragma unroll
            for (int e = 0; e < 4; e++) s[nb][e] = 0.f;
#pragma unroll
        for (int ks = 0; ks < 8; ks++) {
            const int kb = ks * 8;
            unsigned a0 = __float_as_uint(Qs[(kb + t    ) * 68 + r0 + g    ]);
            unsigned a1 = __float_as_uint(Qs[(kb + t    ) * 68 + r0 + g + 8]);
            unsigned a2 = __float_as_uint(Qs[(kb + t + 4) * 68 + r0 + g    ]);
            unsigned a3 = __float_as_uint(Qs[(kb + t + 4) * 68 + r0 + g + 8]);
#pragma unroll
            for (int nb = 0; nb < 8; nb++) {
                unsigned b0 = __float_as_uint(Ks[(kb + t    ) * 68 + nb * 8 + g]);
                unsigned b1 = __float_as_uint(Ks[(kb + t + 4) * 68 + nb * 8 + g]);
                mma_tf32(s[nb][0], s[nb][1], s[nb][2], s[nb][3], a0, a1, a2, a3, b0, b1);
            }
        }

#pragma unroll
        for (int nb = 0; nb < 8; nb++) {
            float2 ba = *(const float2*)(bias_ra + m0 + nb * 8 + 2 * t);
            float2 bb = *(const float2*)(bias_rb + m0 + nb * 8 + 2 * t);
            s[nb][0] = s[nb][0] * ATT_SCALE + ba.x;
            s[nb][1] = s[nb][1] * ATT_SCALE + ba.y;
            s[nb][2] = s[nb][2] * ATT_SCALE + bb.x;
            s[nb][3] = s[nb][3] * ATT_SCALE + bb.y;
        }

        float tm0 = -1e30f, tm1 = -1e30f;
#pragma unroll
        for (int nb = 0; nb < 8; nb++) {
            tm0 = fmaxf(tm0, fmaxf(s[nb][0], s[nb][1]));
            tm1 = fmaxf(tm1, fmaxf(s[nb][2], s[nb][3]));
        }
        tm0 = fmaxf(tm0, __shfl_xor_sync(0xffffffffu, tm0, 1));
        tm0 = fmaxf(tm0, __shfl_xor_sync(0xffffffffu, tm0, 2));
        tm1 = fmaxf(tm1, __shfl_xor_sync(0xffffffffu, tm1, 1));
        tm1 = fmaxf(tm1, __shfl_xor_sync(0xffffffffu, tm1, 2));
        const float mn0 = fmaxf(m_st[0], tm0);
        const float mn1 = fmaxf(m_st[1], tm1);

        float ls0 = 0.f, ls1 = 0.f;
#pragma unroll
        for (int nb = 0; nb < 8; nb++) {
            float p0 = __expf(s[nb][0] - mn0);
            float p1 = __expf(s[nb][1] - mn0);
            float p2 = __expf(s[nb][2] - mn1);
            float p3 = __expf(s[nb][3] - mn1);
            ls0 += p0 + p1;
            ls1 += p2 + p3;
            const int col = nb * 8 + 2 * t;
            Psw[(col    ) * 24 + g    ] = __uint_as_float(f2tf32(p0));
            Psw[(col + 1) * 24 + g    ] = __uint_as_float(f2tf32(p1));
            Psw[(col    ) * 24 + g + 8] = __uint_as_float(f2tf32(p2));
            Psw[(col + 1) * 24 + g + 8] = __uint_as_float(f2tf32(p3));
        }
        ls0 += __shfl_xor_sync(0xffffffffu, ls0, 1);
        ls0 += __shfl_xor_sync(0xffffffffu, ls0, 2);
        ls1 += __shfl_xor_sync(0xffffffffu, ls1, 1);
        ls1 += __shfl_xor_sync(0xffffffffu, ls1, 2);

        const float al0 = __expf(m_st[0] - mn0);
        const float al1 = __expf(m_st[1] - mn1);
        l_st[0] = l_st[0] * al0 + ls0;
        l_st[1] = l_st[1] * al1 + ls1;
        m_st[0] = mn0; m_st[1] = mn1;
#pragma unroll
        for (int nb = 0; nb < 8; nb++) {
            o[nb][0] *= al0; o[nb][1] *= al0;
            o[nb][2] *= al1; o[nb][3] *= al1;
        }
        __syncwarp();

#pragma unroll
        for (int ks = 0; ks < 8; ks++) {
            const int kb = ks * 8;
            unsigned a0 = __float_as_uint(Psw[(kb + t    ) * 24 + g    ]);
            unsigned a1 = __float_as_uint(Psw[(kb + t    ) * 24 + g + 8]);
            unsigned a2 = __float_as_uint(Psw[(kb + t + 4) * 24 + g    ]);
            unsigned a3 = __float_as_uint(Psw[(kb + t + 4) * 24 + g + 8]);
#pragma unroll
            for (int nb = 0; nb < 8; nb++) {
                unsigned b0 = __float_as_uint(Vs[(kb + t    ) * 68 + nb * 8 + g]);
                unsigned b1 = __float_as_uint(Vs[(kb + t + 4) * 68 + nb * 8 + g]);
                mma_tf32(o[nb][0], o[nb][1], o[nb][2], o[nb][3], a0, a1, a2, a3, b0, b1);
            }
        }
    }

    const float inv0 = 1.0f / l_st[0];
    const float inv1 = 1.0f / l_st[1];
    float* oa = O + (size_t)qra * HID + h * HD;
    float* ob = oa + (size_t)8 * HID;
#pragma unroll
    for (int nb = 0; nb < 8; nb++) {
        const int col = nb * 8 + 2 * t;
        *(float2*)(oa + col) = make_float2(o[nb][0] * inv0, o[nb][1] * inv0);
        *(float2*)(ob + col) = make_float2(o[nb][2] * inv1, o[nb][3] * inv1);
    }
}

// ---------------------------------------------------------------------------
extern "C" void kernel_launch(void* const* d_in, const int* in_sizes, int n_in,
                              void* d_out, int out_size)
{
    const float* x  = (const float*)d_in[0];
    const float* eb = (const float*)d_in[1];
    const float* Wq = (const float*)d_in[2];
    const float* Wk = (const float*)d_in[3];
    const float* Wv = (const float*)d_in[4];
    const float* bv = (const float*)d_in[5];
    const float* Wo = (const float*)d_in[6];
    const float* bo = (const float*)d_in[7];
    float* out = (float*)d_out;

    float *Qp, *Kp, *Vp, *Op;
    cudaGetSymbolAddress((void**)&Qp, g_Q);
    cudaGetSymbolAddress((void**)&Kp, g_K);
    cudaGetSymbolAddress((void**)&Vp, g_V);
    cudaGetSymbolAddress((void**)&Op, g_O);

    cudaFuncSetAttribute(gemm_qkv,
                         cudaFuncAttributeMaxDynamicSharedMemorySize, GEMM_SMEM);
    cudaFuncSetAttribute(gemm_one,
                         cudaFuncAttributeMaxDynamicSharedMemorySize, GEMM_SMEM);
    cudaFuncSetAttribute(attn_mma,
                         cudaFuncAttributeMaxDynamicSharedMemorySize, ATTN_SMEM);

    gemm_qkv<<<dim3(HID / 128, MROWS / 128, 3), 256, GEMM_SMEM>>>(
        x, Wq, Wk, Wv, bv, Qp, Kp, Vp);

    attn_mma<<<dim3(SEQ / 64, NHEAD, BATCH), 128, ATTN_SMEM>>>(Qp, Kp, Vp, eb, Op);

    gemm_one<<<dim3(HID / 128, MROWS / 128), 256, GEMM_SMEM>>>(Op, Wo, bo, out);
}